// round 7
// baseline (speedup 1.0000x reference)
#include <cuda_runtime.h>
#include <cstdint>

#define BATCH   4
#define KCLS    64
#define NSHOT   32
#define DIM     128
#define MTEST   4096
#define TRN     (KCLS * NSHOT)      // 2048 train rows per batch
#define TM      128                 // test tile per block
#define TN      128                 // train rows per chunk (4 classes)
#define NCHUNK  (TRN / TN)          // 16

// ---------------------------------------------------------------------------
// Single fused kernel:
//   score(m, n) = dot(test_raw[m], train_raw[n]) * invnorm(train[n])
//   (test normalization is a positive per-test scalar -> argmax-invariant,
//    dropped; train normalization folds into a per-train-row scale)
//   class_score(m, k) = max over 32 shots; label = first argmax over k.
//
// OUTPUT IS float32 (labels stored as floats) — this was the rounds-5/6 bug:
// int bit patterns of small labels are float denormals ~= 0 -> rel_err 1.0.
//
// One block = 128 tests x one batch. 256 threads.
// SMEM (transposed [d][...] so compute reads are depth-row uniform):
//   teS : [128][128]  test  tile, block c = m>>2 stored at c ^ (d>>2)
//   trS : [128][128]  train tile, block c = n>>2 stored at c ^ (d>>2)
//   invnS: [128]      1/||train row|| for the current chunk
// ---------------------------------------------------------------------------
extern __shared__ __align__(16) float smem[];

__global__ __launch_bounds__(256, 1)
void ms_kernel(const float* __restrict__ train,
               const float* __restrict__ test,
               float* __restrict__ out) {
    float* teS   = smem;                    // 64 KB
    float* trS   = smem + DIM * TM;         // 64 KB
    float* invnS = smem + 2 * DIM * TM;     // 512 B

    const int tid  = threadIdx.x;
    const int lane = tid & 31;
    const int warp = tid >> 5;
    const int tx   = tid & 15;              // train-column group (16 lanes/class)
    const int ty   = tid >> 4;              // test-row group (8 tests each)
    const int b      = blockIdx.y;
    const int m_base = blockIdx.x * TM;

    const float* teg = test  + ((size_t)b * MTEST + m_base) * DIM;
    const float* trg = train + (size_t)b * TRN * DIM;

    // ---- load test tile once: transposed + swizzled ---------------------
    #pragma unroll
    for (int r = 0; r < 16; ++r) {
        int m = warp * 16 + r;
        float4 v = *(const float4*)(teg + (size_t)m * DIM + lane * 4);
        int m4 = m >> 2, mo = m & 3;
        float vv[4] = {v.x, v.y, v.z, v.w};
        #pragma unroll
        for (int i = 0; i < 4; ++i)
            teS[(lane * 4 + i) * TM + ((m4 ^ lane) << 2) + mo] = vv[i];
    }

    float bestv[8];
    int   bestk[8];
    #pragma unroll
    for (int i = 0; i < 8; ++i) { bestv[i] = -3.402823466e38f; bestk[i] = 0; }

    for (int chunk = 0; chunk < NCHUNK; ++chunk) {
        const int rowBase = chunk * TN;

        __syncthreads();   // iter 0: te ready; else: previous compute done

        // ---- load 128 train rows: transposed + swizzled + row invnorm ---
        #pragma unroll
        for (int r = 0; r < 16; ++r) {
            int n = warp * 16 + r;
            float4 v = *(const float4*)(trg + (size_t)(rowBase + n) * DIM + lane * 4);
            // row sum-of-squares across the whole warp (each lane holds 4 d's)
            float s = v.x * v.x + v.y * v.y + v.z * v.z + v.w * v.w;
            #pragma unroll
            for (int o = 16; o; o >>= 1) s += __shfl_xor_sync(0xffffffffu, s, o);
            if (lane == 0) invnS[n] = 1.0f / fmaxf(sqrtf(s), 1e-8f);

            int n4 = n >> 2, no = n & 3;
            float vv[4] = {v.x, v.y, v.z, v.w};
            #pragma unroll
            for (int i = 0; i < 4; ++i)
                trS[(lane * 4 + i) * TN + ((n4 ^ lane) << 2) + no] = vv[i];
        }
        __syncthreads();

        // ---- scalar FFMA mainloop: 8 tests x 8 trains per thread --------
        float acc[8][8];
        #pragma unroll
        for (int i = 0; i < 8; ++i)
            #pragma unroll
            for (int j = 0; j < 8; ++j) acc[i][j] = 0.0f;

        const int txh = tx >> 1;            // block within class octet
        const int txo = (tx & 1) << 1;      // float2 offset within block

        #pragma unroll 2
        for (int kk = 0; kk < DIM; ++kk) {
            int s = kk >> 2;
            const float* teR = teS + kk * TM;
            const float* trR = trS + kk * TN;

            // tests 8ty..8ty+7 (two 16B row-uniform loads per warp half)
            float4 a0 = *(const float4*)(teR + (((2 * ty + 0) ^ s) << 2));
            float4 a1 = *(const float4*)(teR + (((2 * ty + 1) ^ s) << 2));
            // trains 32q + 2tx, 2tx+1 for q = 0..3 (conflict-free float2s)
            float2 b0 = *(const float2*)(trR + ((( 0 + txh) ^ s) << 2) + txo);
            float2 b1 = *(const float2*)(trR + ((( 8 + txh) ^ s) << 2) + txo);
            float2 b2 = *(const float2*)(trR + (((16 + txh) ^ s) << 2) + txo);
            float2 b3 = *(const float2*)(trR + (((24 + txh) ^ s) << 2) + txo);

            float A[8] = {a0.x, a0.y, a0.z, a0.w, a1.x, a1.y, a1.z, a1.w};
            float B[8] = {b0.x, b0.y, b1.x, b1.y, b2.x, b2.y, b3.x, b3.y};
            #pragma unroll
            for (int i = 0; i < 8; ++i)
                #pragma unroll
                for (int j = 0; j < 8; ++j)
                    acc[i][j] += A[i] * B[j];
        }

        // ---- fold inv-norms, class max over 32 shots (16 lanes x 2),
        //      running argmax (ascending class order, strict > = first-max)
        float w[8];
        #pragma unroll
        for (int q = 0; q < 4; ++q) {
            w[2 * q]     = invnS[q * 32 + 2 * tx];
            w[2 * q + 1] = invnS[q * 32 + 2 * tx + 1];
        }

        #pragma unroll
        for (int i = 0; i < 8; ++i) {
            #pragma unroll
            for (int q = 0; q < 4; ++q) {
                float v = fmaxf(acc[i][2 * q]     * w[2 * q],
                                acc[i][2 * q + 1] * w[2 * q + 1]);
                #pragma unroll
                for (int o = 1; o <= 8; o <<= 1)   // reduce across 16 tx lanes
                    v = fmaxf(v, __shfl_xor_sync(0xffffffffu, v, o));
                int cls = chunk * 4 + q;
                if (v > bestv[i]) { bestv[i] = v; bestk[i] = cls; }
            }
        }
    }

    // all 16 tx lanes hold identical results; tx==0 writes its 8 tests.
    // Labels are written as FLOAT32 (the output dtype).
    if (tx == 0) {
        float* o = out + ((size_t)b * MTEST + m_base + ty * 8);
        #pragma unroll
        for (int i = 0; i < 8; ++i) o[i] = (float)bestk[i];
    }
}

// ---------------------------------------------------------------------------
extern "C" void kernel_launch(void* const* d_in, const int* in_sizes, int n_in,
                              void* d_out, int out_size) {
    const float* train;
    const float* test;
    if (in_sizes[0] == BATCH * KCLS * NSHOT * DIM) {
        train = (const float*)d_in[0];
        test  = (const float*)d_in[1];
    } else {
        train = (const float*)d_in[1];
        test  = (const float*)d_in[0];
    }
    float* out = (float*)d_out;

    const int smem_bytes = (2 * DIM * TM + TN) * (int)sizeof(float); // ~128.5 KB
    cudaFuncSetAttribute(ms_kernel,
                         cudaFuncAttributeMaxDynamicSharedMemorySize,
                         smem_bytes);

    dim3 grid(MTEST / TM, BATCH);
    ms_kernel<<<grid, 256, smem_bytes>>>(train, test, out);
}

// round 8
// speedup vs baseline: 1.1097x; 1.1097x over previous
#include <cuda_runtime.h>
#include <cstdint>

#define BATCH   4
#define KCLS    64
#define NSHOT   32
#define DIM     128
#define MTEST   4096
#define TRN     (KCLS * NSHOT)      // 2048 train rows per batch
#define TM      128                 // test tile per block
#define TN      128                 // train rows per chunk (4 classes)
#define NCHUNK  (TRN / TN)          // 16

// ---------------------------------------------------------------------------
// Fused kernel (verified in Round 7), inner loop upgraded to packed
// fma.rn.f32x2 (2 FMAs/instruction, PTX ISA 8.6, sm_100+):
//   score(m, n) = dot(test_raw[m], train_raw[n]) * invnorm(train[n])
//   class_score(m, k) = max over 32 shots; label = first argmax over k.
//   (test normalization dropped: positive per-test scalar, argmax-invariant)
// Output dtype: float32 labels.
//
// Pairing is over TRAINS: the float2 B loads (shots 2tx,2tx+1 of a class)
// are already adjacent in smem -> loaded directly as 64-bit packed operands.
// A (test) values are duplicated (a,a) once per kk via mov.b64.
// ---------------------------------------------------------------------------

__device__ __forceinline__ void ffma2(unsigned long long& d,
                                      unsigned long long a,
                                      unsigned long long b) {
    asm("fma.rn.f32x2 %0, %1, %2, %0;" : "+l"(d) : "l"(a), "l"(b));
}
__device__ __forceinline__ unsigned long long dup2(float a) {
    unsigned long long r;
    asm("mov.b64 %0, {%1, %1};" : "=l"(r) : "f"(a));
    return r;
}
__device__ __forceinline__ float2 u2f2(unsigned long long u) {
    float2 f;
    asm("mov.b64 {%0, %1}, %2;" : "=f"(f.x), "=f"(f.y) : "l"(u));
    return f;
}

extern __shared__ __align__(16) float smem[];

__global__ __launch_bounds__(256, 1)
void ms_kernel(const float* __restrict__ train,
               const float* __restrict__ test,
               float* __restrict__ out) {
    float* teS   = smem;                    // 64 KB
    float* trS   = smem + DIM * TM;         // 64 KB
    float* invnS = smem + 2 * DIM * TM;     // 512 B

    const int tid  = threadIdx.x;
    const int lane = tid & 31;
    const int warp = tid >> 5;
    const int tx   = tid & 15;              // train-column group (16 lanes/class)
    const int ty   = tid >> 4;              // test-row group (8 tests each)
    const int b      = blockIdx.y;
    const int m_base = blockIdx.x * TM;

    const float* teg = test  + ((size_t)b * MTEST + m_base) * DIM;
    const float* trg = train + (size_t)b * TRN * DIM;

    // ---- load test tile once: transposed + swizzled ---------------------
    #pragma unroll
    for (int r = 0; r < 16; ++r) {
        int m = warp * 16 + r;
        float4 v = *(const float4*)(teg + (size_t)m * DIM + lane * 4);
        int m4 = m >> 2, mo = m & 3;
        float vv[4] = {v.x, v.y, v.z, v.w};
        #pragma unroll
        for (int i = 0; i < 4; ++i)
            teS[(lane * 4 + i) * TM + ((m4 ^ lane) << 2) + mo] = vv[i];
    }

    float bestv[8];
    int   bestk[8];
    #pragma unroll
    for (int i = 0; i < 8; ++i) { bestv[i] = -3.402823466e38f; bestk[i] = 0; }

    for (int chunk = 0; chunk < NCHUNK; ++chunk) {
        const int rowBase = chunk * TN;

        __syncthreads();   // iter 0: te ready; else: previous compute done

        // ---- load 128 train rows: transposed + swizzled + row invnorm ---
        #pragma unroll
        for (int r = 0; r < 16; ++r) {
            int n = warp * 16 + r;
            float4 v = *(const float4*)(trg + (size_t)(rowBase + n) * DIM + lane * 4);
            float s = v.x * v.x + v.y * v.y + v.z * v.z + v.w * v.w;
            #pragma unroll
            for (int o = 16; o; o >>= 1) s += __shfl_xor_sync(0xffffffffu, s, o);
            if (lane == 0) invnS[n] = 1.0f / fmaxf(sqrtf(s), 1e-8f);

            int n4 = n >> 2, no = n & 3;
            float vv[4] = {v.x, v.y, v.z, v.w};
            #pragma unroll
            for (int i = 0; i < 4; ++i)
                trS[(lane * 4 + i) * TN + ((n4 ^ lane) << 2) + no] = vv[i];
        }
        __syncthreads();

        // ---- FFMA2 mainloop: 8 tests x 4 train-PAIRS per thread ---------
        // acc2[i][q] = packed (score(test i, shot 2tx of class q),
        //                      score(test i, shot 2tx+1 of class q))
        unsigned long long acc2[8][4];
        #pragma unroll
        for (int i = 0; i < 8; ++i)
            #pragma unroll
            for (int j = 0; j < 4; ++j) acc2[i][j] = 0ULL;

        const int txh = tx >> 1;            // block within class octet
        const int txo = (tx & 1) << 1;      // float2 offset within block

        #pragma unroll 4
        for (int kk = 0; kk < DIM; ++kk) {
            int s = kk >> 2;
            const float* teR = teS + kk * TM;
            const float* trR = trS + kk * TN;

            // tests 8ty..8ty+7 (two 16B row-uniform loads per warp half)
            float4 a0 = *(const float4*)(teR + (((2 * ty + 0) ^ s) << 2));
            float4 a1 = *(const float4*)(teR + (((2 * ty + 1) ^ s) << 2));
            // train pairs (2tx, 2tx+1) of classes 0..3, loaded packed (8B aligned)
            unsigned long long B2[4];
            B2[0] = *(const unsigned long long*)(trR + ((( 0 + txh) ^ s) << 2) + txo);
            B2[1] = *(const unsigned long long*)(trR + ((( 8 + txh) ^ s) << 2) + txo);
            B2[2] = *(const unsigned long long*)(trR + (((16 + txh) ^ s) << 2) + txo);
            B2[3] = *(const unsigned long long*)(trR + (((24 + txh) ^ s) << 2) + txo);

            float A[8] = {a0.x, a0.y, a0.z, a0.w, a1.x, a1.y, a1.z, a1.w};
            unsigned long long A2[8];
            #pragma unroll
            for (int i = 0; i < 8; ++i) A2[i] = dup2(A[i]);

            #pragma unroll
            for (int i = 0; i < 8; ++i)
                #pragma unroll
                for (int j = 0; j < 4; ++j)
                    ffma2(acc2[i][j], A2[i], B2[j]);
        }

        // ---- fold inv-norms, class max over 32 shots (16 lanes x 2),
        //      running argmax (ascending class order, strict > = first-max)
        float w[8];
        #pragma unroll
        for (int q = 0; q < 4; ++q) {
            w[2 * q]     = invnS[q * 32 + 2 * tx];
            w[2 * q + 1] = invnS[q * 32 + 2 * tx + 1];
        }

        #pragma unroll
        for (int i = 0; i < 8; ++i) {
            #pragma unroll
            for (int q = 0; q < 4; ++q) {
                float2 f = u2f2(acc2[i][q]);
                float v = fmaxf(f.x * w[2 * q], f.y * w[2 * q + 1]);
                #pragma unroll
                for (int o = 1; o <= 8; o <<= 1)   // reduce across 16 tx lanes
                    v = fmaxf(v, __shfl_xor_sync(0xffffffffu, v, o));
                int cls = chunk * 4 + q;
                if (v > bestv[i]) { bestv[i] = v; bestk[i] = cls; }
            }
        }
    }

    // all 16 tx lanes hold identical results; tx==0 writes its 8 tests
    if (tx == 0) {
        float* o = out + ((size_t)b * MTEST + m_base + ty * 8);
        #pragma unroll
        for (int i = 0; i < 8; ++i) o[i] = (float)bestk[i];
    }
}

// ---------------------------------------------------------------------------
extern "C" void kernel_launch(void* const* d_in, const int* in_sizes, int n_in,
                              void* d_out, int out_size) {
    const float* train;
    const float* test;
    if (in_sizes[0] == BATCH * KCLS * NSHOT * DIM) {
        train = (const float*)d_in[0];
        test  = (const float*)d_in[1];
    } else {
        train = (const float*)d_in[1];
        test  = (const float*)d_in[0];
    }
    float* out = (float*)d_out;

    const int smem_bytes = (2 * DIM * TM + TN) * (int)sizeof(float); // ~128.5 KB
    cudaFuncSetAttribute(ms_kernel,
                         cudaFuncAttributeMaxDynamicSharedMemorySize,
                         smem_bytes);

    dim3 grid(MTEST / TM, BATCH);
    ms_kernel<<<grid, 256, smem_bytes>>>(train, test, out);
}

// round 9
// speedup vs baseline: 1.2629x; 1.1381x over previous
#include <cuda_runtime.h>
#include <cstdint>

#define BATCH   4
#define KCLS    64
#define NSHOT   32
#define DIM     128
#define MTEST   4096
#define TRN     (KCLS * NSHOT)      // 2048 train rows per batch
#define TM      128                 // test tile per block
#define TN      128                 // train rows per chunk (4 classes)
#define NCHUNK  (TRN / TN)          // 16
#define THREADS 512                 // 16 warps -> 4 warps/SMSP

// ---------------------------------------------------------------------------
// Fused cosine-sim argmax (verified R7/R8), now at 512 threads/block for
// latency hiding. Inner loop: packed fma.rn.f32x2, 4 tests x 4 train-pairs
// per thread (16 FFMA2 / kk / thread).
//   score(m,n) = dot(test_raw[m], train_raw[n]) * invnorm(train[n])
//   label = first argmax over classes of (max over 32 shots)
// Test normalization dropped (positive scalar, argmax-invariant).
// Output: float32 labels.
// ---------------------------------------------------------------------------

__device__ __forceinline__ void ffma2(unsigned long long& d,
                                      unsigned long long a,
                                      unsigned long long b) {
    asm("fma.rn.f32x2 %0, %1, %2, %0;" : "+l"(d) : "l"(a), "l"(b));
}
__device__ __forceinline__ unsigned long long dup2(float a) {
    unsigned long long r;
    asm("mov.b64 %0, {%1, %1};" : "=l"(r) : "f"(a));
    return r;
}
__device__ __forceinline__ float2 u2f2(unsigned long long u) {
    float2 f;
    asm("mov.b64 {%0, %1}, %2;" : "=f"(f.x), "=f"(f.y) : "l"(u));
    return f;
}

extern __shared__ __align__(16) float smem[];

__global__ __launch_bounds__(THREADS, 1)
void ms_kernel(const float* __restrict__ train,
               const float* __restrict__ test,
               float* __restrict__ out) {
    float* teS   = smem;                    // [128][128] tests  (64 KB)
    float* trS   = smem + DIM * TM;         // [128][128] trains (64 KB)
    float* invnS = smem + 2 * DIM * TM;     // [128]

    const int tid  = threadIdx.x;
    const int lane = tid & 31;
    const int warp = tid >> 5;              // 0..15
    const int tx   = tid & 15;              // train-column group (16 lanes/class)
    const int ty   = tid >> 4;              // test group, 0..31 (4 tests each)
    const int b      = blockIdx.y;
    const int m_base = blockIdx.x * TM;

    const float* teg = test  + ((size_t)b * MTEST + m_base) * DIM;
    const float* trg = train + (size_t)b * TRN * DIM;

    // ---- load test tile once: transposed + swizzled (8 rows per warp) ---
    #pragma unroll
    for (int r = 0; r < 8; ++r) {
        int m = warp * 8 + r;
        float4 v = *(const float4*)(teg + (size_t)m * DIM + lane * 4);
        int m4 = m >> 2, mo = m & 3;
        float vv[4] = {v.x, v.y, v.z, v.w};
        #pragma unroll
        for (int i = 0; i < 4; ++i)
            teS[(lane * 4 + i) * TM + ((m4 ^ lane) << 2) + mo] = vv[i];
    }

    float bestv[4];
    int   bestk[4];
    #pragma unroll
    for (int i = 0; i < 4; ++i) { bestv[i] = -3.402823466e38f; bestk[i] = 0; }

    const int txh = tx >> 1;                // block within class octet (0..7)
    const int txo = (tx & 1) << 1;          // float2 offset within block

    for (int chunk = 0; chunk < NCHUNK; ++chunk) {
        const int rowBase = chunk * TN;

        __syncthreads();   // iter 0: te ready; else: previous compute done

        // ---- load 128 train rows: transposed + swizzled + row invnorm ---
        #pragma unroll
        for (int r = 0; r < 8; ++r) {
            int n = warp * 8 + r;
            float4 v = *(const float4*)(trg + (size_t)(rowBase + n) * DIM + lane * 4);
            float s = v.x * v.x + v.y * v.y + v.z * v.z + v.w * v.w;
            #pragma unroll
            for (int o = 16; o; o >>= 1) s += __shfl_xor_sync(0xffffffffu, s, o);
            if (lane == 0) invnS[n] = 1.0f / fmaxf(sqrtf(s), 1e-8f);

            int n4 = n >> 2, no = n & 3;
            float vv[4] = {v.x, v.y, v.z, v.w};
            #pragma unroll
            for (int i = 0; i < 4; ++i)
                trS[(lane * 4 + i) * TN + ((n4 ^ lane) << 2) + no] = vv[i];
        }
        __syncthreads();

        // ---- FFMA2 mainloop: 4 tests x 4 train-pairs per thread ---------
        // acc2[i][q] = packed (score(test 4ty+i, shot 2tx   of class q),
        //                      score(test 4ty+i, shot 2tx+1 of class q))
        unsigned long long acc2[4][4];
        #pragma unroll
        for (int i = 0; i < 4; ++i)
            #pragma unroll
            for (int j = 0; j < 4; ++j) acc2[i][j] = 0ULL;

        // outer: swizzle phase s = kk>>2 (addresses constant per phase);
        // inner: 4 kk with immediate-offset loads
        #pragma unroll 2
        for (int s = 0; s < DIM / 4; ++s) {
            const float* aP  = teS + (s * 4) * TM + ((ty ^ s) << 2);
            const float* bP0 = trS + (s * 4) * TN + ((( 0 + txh) ^ s) << 2) + txo;
            const float* bP1 = trS + (s * 4) * TN + ((( 8 + txh) ^ s) << 2) + txo;
            const float* bP2 = trS + (s * 4) * TN + (((16 + txh) ^ s) << 2) + txo;
            const float* bP3 = trS + (s * 4) * TN + (((24 + txh) ^ s) << 2) + txo;

            #pragma unroll
            for (int u = 0; u < 4; ++u) {
                float4 a = *(const float4*)(aP + u * TM);   // tests 4ty..4ty+3
                unsigned long long B2[4];
                B2[0] = *(const unsigned long long*)(bP0 + u * TN);
                B2[1] = *(const unsigned long long*)(bP1 + u * TN);
                B2[2] = *(const unsigned long long*)(bP2 + u * TN);
                B2[3] = *(const unsigned long long*)(bP3 + u * TN);

                unsigned long long A2[4];
                A2[0] = dup2(a.x); A2[1] = dup2(a.y);
                A2[2] = dup2(a.z); A2[3] = dup2(a.w);

                #pragma unroll
                for (int i = 0; i < 4; ++i)
                    #pragma unroll
                    for (int j = 0; j < 4; ++j)
                        ffma2(acc2[i][j], A2[i], B2[j]);
            }
        }

        // ---- fold inv-norms, class max over 32 shots (16 lanes x 2),
        //      running argmax (ascending class order, strict > = first-max)
        float w[8];
        #pragma unroll
        for (int q = 0; q < 4; ++q) {
            w[2 * q]     = invnS[q * 32 + 2 * tx];
            w[2 * q + 1] = invnS[q * 32 + 2 * tx + 1];
        }

        #pragma unroll
        for (int i = 0; i < 4; ++i) {
            #pragma unroll
            for (int q = 0; q < 4; ++q) {
                float2 f = u2f2(acc2[i][q]);
                float v = fmaxf(f.x * w[2 * q], f.y * w[2 * q + 1]);
                #pragma unroll
                for (int o = 1; o <= 8; o <<= 1)   // reduce across 16 tx lanes
                    v = fmaxf(v, __shfl_xor_sync(0xffffffffu, v, o));
                int cls = chunk * 4 + q;
                if (v > bestv[i]) { bestv[i] = v; bestk[i] = cls; }
            }
        }
    }

    // all 16 tx lanes hold identical results; tx==0 writes its 4 tests
    if (tx == 0) {
        float* o = out + ((size_t)b * MTEST + m_base + ty * 4);
        #pragma unroll
        for (int i = 0; i < 4; ++i) o[i] = (float)bestk[i];
    }
}

// ---------------------------------------------------------------------------
extern "C" void kernel_launch(void* const* d_in, const int* in_sizes, int n_in,
                              void* d_out, int out_size) {
    const float* train;
    const float* test;
    if (in_sizes[0] == BATCH * KCLS * NSHOT * DIM) {
        train = (const float*)d_in[0];
        test  = (const float*)d_in[1];
    } else {
        train = (const float*)d_in[1];
        test  = (const float*)d_in[0];
    }
    float* out = (float*)d_out;

    const int smem_bytes = (2 * DIM * TM + TN) * (int)sizeof(float); // ~128.5 KB
    cudaFuncSetAttribute(ms_kernel,
                         cudaFuncAttributeMaxDynamicSharedMemorySize,
                         smem_bytes);

    dim3 grid(MTEST / TM, BATCH);
    ms_kernel<<<grid, THREADS, smem_bytes>>>(train, test, out);
}